// round 15
// baseline (speedup 1.0000x reference)
#include <cuda_runtime.h>
#include <cstdint>
#include <cuda_fp16.h>
#include <mma.h>
#include <math.h>

using namespace nvcuda;

#define NTOK 8192
#define DIM  384
#define NEXP 8
#define HID  1536
#define OUTD 384
#define NPAIR (NTOK * 2)

// ---------------- device scratch ----------------
__device__ int     g_counts[NEXP];
__device__ int     g_list[NEXP * NTOK];
__device__ float2  g_gates[NTOK];
__device__ __half  g_x [(size_t)NTOK * DIM];
__device__ __half  g_w1[(size_t)NEXP * DIM * HID];
__device__ __half  g_w2[(size_t)NEXP * HID * OUTD];
__device__ __half  g_h [(size_t)NPAIR * HID];

// ---------------- helpers ----------------
__device__ __forceinline__ void cp16(unsigned smem_dst, const void* gsrc, int srcsize) {
    asm volatile("cp.async.cg.shared.global [%0], [%1], 16, %2;\n"
                 :: "r"(smem_dst), "l"(gsrc), "r"(srcsize) : "memory");
}
__device__ __forceinline__ void cp_commit() {
    asm volatile("cp.async.commit_group;\n" ::: "memory");
}
template<int N>
__device__ __forceinline__ void cp_wait() {
    asm volatile("cp.async.wait_group %0;\n" :: "n"(N) : "memory");
}
__device__ __forceinline__ float gelu_f(float v) {
    return 0.5f * v * (1.0f + erff(v * 0.70710678118654752f));
}

// ---------------- small kernels ----------------
__global__ void zero_counts_kernel() {
    if (threadIdx.x < NEXP) g_counts[threadIdx.x] = 0;
}

__global__ void zero_out_kernel(float* __restrict__ out) {
    int i = blockIdx.x * blockDim.x + threadIdx.x;
    if (i < NTOK * OUTD) out[i] = 0.f;
}

// one pass: x -> g_x, W1 -> g_w1, W2 -> g_w2
#define N4X (NTOK * DIM / 4)
#define N4W (NEXP * DIM * HID / 4)
__global__ void round_all_kernel(const float* __restrict__ x,
                                 const float* __restrict__ W1,
                                 const float* __restrict__ W2,
                                 __half* __restrict__ dx,
                                 __half* __restrict__ dw1,
                                 __half* __restrict__ dw2) {
    int i = blockIdx.x * blockDim.x + threadIdx.x;
    const float* src; __half* dst; int j;
    if (i < N4X)            { src = x;  dst = dx;  j = i; }
    else if (i < N4X + N4W) { src = W1; dst = dw1; j = i - N4X; }
    else if (i < N4X + 2 * N4W) { src = W2; dst = dw2; j = i - N4X - N4W; }
    else return;
    float4 v = ((const float4*)src)[j];
    ((__half2*)dst)[2 * j]     = __floats2half2_rn(v.x, v.y);
    ((__half2*)dst)[2 * j + 1] = __floats2half2_rn(v.z, v.w);
}

__global__ void router_kernel(const float* __restrict__ x,
                              const float* __restrict__ Wg,
                              const float* __restrict__ bg) {
    int warp = (blockIdx.x * blockDim.x + threadIdx.x) >> 5;
    int lane = threadIdx.x & 31;
    if (warp >= NTOK) return;

    const float* xr = x + (size_t)warp * DIM;
    float acc[NEXP];
#pragma unroll
    for (int e = 0; e < NEXP; e++) acc[e] = 0.f;

    for (int d = lane; d < DIM; d += 32) {
        float xv = xr[d];
        const float* wr = Wg + d * NEXP;
#pragma unroll
        for (int e = 0; e < NEXP; e++) acc[e] += xv * wr[e];
    }
#pragma unroll
    for (int e = 0; e < NEXP; e++) {
#pragma unroll
        for (int off = 16; off > 0; off >>= 1)
            acc[e] += __shfl_xor_sync(0xffffffffu, acc[e], off);
    }
    if (lane == 0) {
        float v0 = -1e30f, v1 = -1e30f;
        int   i0 = 0,      i1 = 0;
#pragma unroll
        for (int e = 0; e < NEXP; e++) {
            float v = acc[e] + bg[e];
            if (v > v0)      { v1 = v0; i1 = i0; v0 = v; i0 = e; }
            else if (v > v1) { v1 = v;  i1 = e; }
        }
        float e1 = expf(v1 - v0);
        float inv = 1.0f / (1.0f + e1);
        g_gates[warp] = make_float2(inv, e1 * inv);

        int p0 = atomicAdd(&g_counts[i0], 1);
        g_list[i0 * NTOK + p0] = warp * 2;
        int p1 = atomicAdd(&g_counts[i1], 1);
        g_list[i1 * NTOK + p1] = warp * 2 + 1;
    }
}

// ================= gemm1: A-resident =======================================
// CTA = (m-block 128, n-half 768, expert). A (gathered x rows, 128x384 fp16)
// resident in smem; B streamed in 64x64 chunks, double-buffered.
// h = gelu(A @ W1[e] + b1[e]) -> g_h (fp16)
#define AR_LD   392                 // 384+8 halves
#define A_RES_H (128 * AR_LD)       // 50176 halves
#define B1_LD   72
#define B1_ST_H (64 * B1_LD)        // 4608 halves
#define PATCH_LD 36                 // multiple of 4 (WMMA fp32 ldm requirement)
#define PATCH_F  (32 * PATCH_LD)    // 1152 floats per warp
#define SOUT_OFF_B ((A_RES_H + 2 * B1_ST_H) * 2)          // 118784
#define ENTRY_OFF_B (SOUT_OFF_B + 8 * PATCH_F * 4)        // +36864 = 155648
#define DSM1_BYTES (ENTRY_OFF_B + 512)                    // 156160

__global__ __launch_bounds__(256)
void gemm1_kernel(const float* __restrict__ b1) {
    const int e  = blockIdx.z;
    const int M  = g_counts[e];
    const int m0 = blockIdx.x * 128;
    if (m0 >= M) return;
    const int nh0 = blockIdx.y * 768;     // n-half base

    extern __shared__ __align__(16) __half dsm[];
    float* sOutF = (float*)((char*)dsm + SOUT_OFF_B);
    int* sEntry  = (int*)((char*)dsm + ENTRY_OFF_B);

    const int tid = threadIdx.x;
    const int w = tid >> 5, lane = tid & 31;
    if (tid < 128) {
        int r = m0 + tid;
        sEntry[tid] = (r < M) ? g_list[e * NTOK + r] : -1;
    }
    __syncthreads();

    unsigned smem_u32 = (unsigned)__cvta_generic_to_shared(dsm);
    const __half* We = g_w1 + (size_t)e * DIM * HID;

    // ---- A gather: 2 thr/row, 24 x 16B each ----
    {
        const int arow = tid >> 1;
        const int aoff = (tid & 1) * 192;   // halves
        const int aentry = sEntry[arow];
        const __half* ag = g_x + (size_t)(aentry < 0 ? 0 : (aentry >> 1)) * DIM + aoff;
        const int asz = aentry < 0 ? 0 : 16;
        unsigned abase = smem_u32 + (unsigned)((arow * AR_LD + aoff) * 2);
#pragma unroll
        for (int i = 0; i < 24; i++)
            cp16(abase + i * 16, ag + i * 8, asz);
    }

    // ---- B chunk mapping: 4 thr/row, 2 x 16B each ----
    const int br = tid >> 2;
    const int bh = (tid & 3) * 16;

    auto issue_b = [&](int c) {
        int j = c / 6, kb = c - j * 6;
        unsigned b0 = smem_u32 + (unsigned)((A_RES_H + (c & 1) * B1_ST_H) * 2);
        const __half* bp = We + (size_t)(kb * 64 + br) * HID + nh0 + j * 64 + bh;
        cp16(b0 + (unsigned)((br * B1_LD + bh) * 2), bp, 16);
        cp16(b0 + (unsigned)((br * B1_LD + bh + 8) * 2), bp + 8, 16);
        cp_commit();
    };

    issue_b(0);   // group0 = A + B chunk0
    issue_b(1);

    const int wm = (w & 3) * 32;
    const int wn = (w >> 2) * 32;
    float* patch = sOutF + w * PATCH_F;

    wmma::fragment<wmma::accumulator, 16, 16, 16, float> c[2][2];

    for (int cc = 0; cc < 72; cc++) {
        const int j = cc / 6, kb = cc - j * 6;
        if (cc == 71) cp_wait<0>(); else cp_wait<1>();
        __syncthreads();

        if (kb == 0) {
#pragma unroll
            for (int i = 0; i < 2; i++)
#pragma unroll
                for (int jj = 0; jj < 2; jj++) wmma::fill_fragment(c[i][jj], 0.f);
        }

        const __half* sB = dsm + A_RES_H + (cc & 1) * B1_ST_H;
#pragma unroll
        for (int ks = 0; ks < 4; ks++) {
            wmma::fragment<wmma::matrix_a, 16, 16, 16, __half, wmma::row_major> a[2];
            wmma::fragment<wmma::matrix_b, 16, 16, 16, __half, wmma::row_major> b[2];
            const int k = kb * 64 + ks * 16;
            wmma::load_matrix_sync(a[0], dsm + (wm) * AR_LD + k, AR_LD);
            wmma::load_matrix_sync(a[1], dsm + (wm + 16) * AR_LD + k, AR_LD);
            wmma::load_matrix_sync(b[0], sB + ks * 16 * B1_LD + wn, B1_LD);
            wmma::load_matrix_sync(b[1], sB + ks * 16 * B1_LD + wn + 16, B1_LD);
#pragma unroll
            for (int i = 0; i < 2; i++) {
                wmma::mma_sync(c[i][0], a[i], b[0], c[i][0]);
                wmma::mma_sync(c[i][1], a[i], b[1], c[i][1]);
            }
        }
        __syncthreads();
        if (cc + 2 < 72) issue_b(cc + 2);

        if (kb == 5) {
            // warp-private epilogue for n-block j (ldm=36: multiple of 4)
#pragma unroll
            for (int i = 0; i < 2; i++)
#pragma unroll
                for (int jj = 0; jj < 2; jj++)
                    wmma::store_matrix_sync(patch + i * 16 * PATCH_LD + jj * 16,
                                            c[i][jj], PATCH_LD, wmma::mem_row_major);
            __syncwarp();
            const int m = wm + lane;
            const int entry = sEntry[m];
            if (entry >= 0) {
                const int n0g = nh0 + j * 64 + wn;
                const float* be = b1 + e * HID + n0g;
                __half2 hb[16];
#pragma unroll
                for (int q = 0; q < 16; q++) {
                    float t0 = gelu_f(patch[lane * PATCH_LD + 2 * q]     + be[2 * q]);
                    float t1 = gelu_f(patch[lane * PATCH_LD + 2 * q + 1] + be[2 * q + 1]);
                    hb[q] = __floats2half2_rn(t0, t1);
                }
                float4* dst = (float4*)(g_h + (size_t)entry * HID + n0g);
                const float4* srcv = (const float4*)hb;
#pragma unroll
                for (int q = 0; q < 4; q++) dst[q] = srcv[q];
            }
        }
    }
}

// ================= gemm2: R11 champion config ==============================
// out[token] += gate * (gather(g_h) @ W2[e] + b2[e])   (2 atomic adds/elem)
#define LDA2 72
#define LDB2 72
#define LDO2 68
#define A2_ST (128 * LDA2)              // 9216 halves
#define B2_ST (64 * LDB2)               // 4608 halves
#define ST2_H (A2_ST + B2_ST)           // 13824 halves
#define DSM2_BYTES (2 * ST2_H * 2 + 512)

__global__ __launch_bounds__(256, 3)
void gemm2_kernel(const float* __restrict__ b2, float* __restrict__ out) {
    const int e  = blockIdx.z;
    const int M  = g_counts[e];
    const int m0 = blockIdx.x * 128;
    if (m0 >= M) return;
    const int n0 = blockIdx.y * 64;
    constexpr int nk = HID / 64;

    extern __shared__ __align__(16) __half dsm[];
    int* sEntry = (int*)(dsm + 2 * ST2_H);

    const int tid = threadIdx.x;
    if (tid < 128) {
        int r = m0 + tid;
        sEntry[tid] = (r < M) ? g_list[e * NTOK + r] : -1;
    }
    __syncthreads();

    const __half* We = g_w2 + (size_t)e * HID * OUTD;

    const int ar = tid >> 1;
    const int ah = (tid & 1) * 32;
    const int br = tid >> 2;
    const int bh = (tid & 3) * 16;

    const int aentry = sEntry[ar];
    const __half* ag = g_h + (size_t)(aentry < 0 ? 0 : aentry) * HID + ah;
    const int asz = aentry < 0 ? 0 : 16;
    const __half* bgp = We + (size_t)br * OUTD + n0 + bh;

    unsigned smem_u32 = (unsigned)__cvta_generic_to_shared(dsm);

    auto issue = [&](int kc) {
        unsigned s0 = smem_u32 + (unsigned)((kc & 1) * (ST2_H * 2));
        const __half* ap = ag + kc * 64;
#pragma unroll
        for (int i = 0; i < 4; i++)
            cp16(s0 + (unsigned)((ar * LDA2 + ah + i * 8) * 2), ap + i * 8, asz);
        unsigned b0 = s0 + (unsigned)(A2_ST * 2);
        const __half* bp = bgp + (size_t)kc * 64 * OUTD;
#pragma unroll
        for (int i = 0; i < 2; i++)
            cp16(b0 + (unsigned)((br * LDB2 + bh + i * 8) * 2), bp + i * 8, 16);
        cp_commit();
    };

    wmma::fragment<wmma::accumulator, 16, 16, 16, float> c[2][2];
#pragma unroll
    for (int i = 0; i < 2; i++)
#pragma unroll
        for (int j = 0; j < 2; j++) wmma::fill_fragment(c[i][j], 0.f);

    const int w  = tid >> 5;
    const int wm = (w & 3) * 32;
    const int wn = (w >> 2) * 32;

    issue(0);
    issue(1);

    for (int kc = 0; kc < nk; kc++) {
        if (kc == nk - 1) cp_wait<0>(); else cp_wait<1>();
        __syncthreads();

        const __half* sA = dsm + (kc & 1) * ST2_H;
        const __half* sB = sA + A2_ST;
#pragma unroll
        for (int ks = 0; ks < 4; ks++) {
            wmma::fragment<wmma::matrix_a, 16, 16, 16, __half, wmma::row_major> a[2];
            wmma::fragment<wmma::matrix_b, 16, 16, 16, __half, wmma::row_major> b[2];
            wmma::load_matrix_sync(a[0], sA + wm * LDA2 + ks * 16, LDA2);
            wmma::load_matrix_sync(a[1], sA + (wm + 16) * LDA2 + ks * 16, LDA2);
            wmma::load_matrix_sync(b[0], sB + ks * 16 * LDB2 + wn, LDB2);
            wmma::load_matrix_sync(b[1], sB + ks * 16 * LDB2 + wn + 16, LDB2);
#pragma unroll
            for (int i = 0; i < 2; i++) {
                wmma::mma_sync(c[i][0], a[i], b[0], c[i][0]);
                wmma::mma_sync(c[i][1], a[i], b[1], c[i][1]);
            }
        }
        __syncthreads();
        if (kc + 2 < nk) issue(kc + 2);
    }

    float* sOut = (float*)dsm;
#pragma unroll
    for (int i = 0; i < 2; i++)
#pragma unroll
        for (int j = 0; j < 2; j++)
            wmma::store_matrix_sync(sOut + (wm + i * 16) * LDO2 + wn + j * 16,
                                    c[i][j], LDO2, wmma::mem_row_major);
    __syncthreads();

    const float* be = b2 + e * OUTD + n0;
    for (int i = tid; i < 128 * 64; i += 256) {
        int r = i >> 6, cc = i & 63;
        int entry = sEntry[r];
        if (entry >= 0) {
            float v = sOut[r * LDO2 + cc] + be[cc];
            int tok = entry >> 1;
            float2 gg = g_gates[tok];
            float gate = (entry & 1) ? gg.y : gg.x;
            atomicAdd(out + (size_t)tok * OUTD + n0 + cc, v * gate);
        }
    }
}

// ---------------- launch ----------------
extern "C" void kernel_launch(void* const* d_in, const int* in_sizes, int n_in,
                              void* d_out, int out_size) {
    const float* x  = (const float*)d_in[0];
    const float* Wg = (const float*)d_in[1];
    const float* bg = (const float*)d_in[2];
    const float* W1 = (const float*)d_in[3];
    const float* b1 = (const float*)d_in[4];
    const float* W2 = (const float*)d_in[5];
    const float* b2 = (const float*)d_in[6];
    float* out = (float*)d_out;

    static bool attr_done = false;
    if (!attr_done) {
        cudaFuncSetAttribute(gemm1_kernel,
                             cudaFuncAttributeMaxDynamicSharedMemorySize, DSM1_BYTES);
        cudaFuncSetAttribute(gemm2_kernel,
                             cudaFuncAttributeMaxDynamicSharedMemorySize, DSM2_BYTES);
        attr_done = true;
    }

    __half *gx, *gw1, *gw2;
    cudaGetSymbolAddress((void**)&gx,  g_x);
    cudaGetSymbolAddress((void**)&gw1, g_w1);
    cudaGetSymbolAddress((void**)&gw2, g_w2);

    zero_counts_kernel<<<1, 32>>>();
    router_kernel<<<(NTOK * 32) / 256, 256>>>(x, Wg, bg);
    zero_out_kernel<<<(NTOK * OUTD + 255) / 256, 256>>>(out);
    round_all_kernel<<<(N4X + 2 * N4W + 255) / 256, 256>>>(x, W1, W2, gx, gw1, gw2);
    gemm1_kernel<<<dim3(NTOK / 128, 2, NEXP), 256, DSM1_BYTES>>>(b1);
    gemm2_kernel<<<dim3(NTOK / 128, OUTD / 64, NEXP), 256, DSM2_BYTES>>>(b2, out);
}